// round 7
// baseline (speedup 1.0000x reference)
#include <cuda_runtime.h>
#include <cstdint>

#define NB 8
#define NC 512
#define NT 1024
#define NHEADS 8
#define NCH 64
#define NGROUPS 32
#define NGC 16

// ---------------- scratch (alloc-free: __device__ globals) ----------------
// g_xn / g_attn: B-frag-ready tiled layout [b][kt=16][nt=8][4096 words]
__device__ float g_xn[(size_t)NB * NC * NT];        // 16 MB
__device__ float g_wq[(size_t)3 * NC * NC];         // 3 MB, A-frag-ready
__device__ float g_wp[(size_t)NC * NC];             // 1 MB, A-frag-ready
__device__ float g_qkv[(size_t)NB * 3 * NC * NT];   // 48 MB, natural [b][3c][t]
__device__ float g_attn[(size_t)NB * NC * NT];      // 16 MB

// ---------------- helpers ----------------
__device__ __forceinline__ uint32_t f2tf32(float f) {
    uint32_t r;
    asm("cvt.rna.tf32.f32 %0, %1;" : "=r"(r) : "f"(f));
    return r;
}
__device__ __forceinline__ float tf32f(float f) { return __uint_as_float(f2tf32(f)); }
__device__ __forceinline__ void mma_tf32(float* d, const uint32_t* a, const uint32_t* b) {
    asm volatile(
        "mma.sync.aligned.m16n8k8.row.col.f32.tf32.tf32.f32 "
        "{%0,%1,%2,%3}, {%4,%5,%6,%7}, {%8,%9}, {%0,%1,%2,%3};"
        : "+f"(d[0]), "+f"(d[1]), "+f"(d[2]), "+f"(d[3])
        : "r"(a[0]), "r"(a[1]), "r"(a[2]), "r"(a[3]), "r"(b[0]), "r"(b[1]));
}
__device__ __forceinline__ void cp16(uint32_t dst, const void* src) {
    asm volatile("cp.async.cg.shared.global [%0], [%1], 16;" :: "r"(dst), "l"(src));
}
__device__ __forceinline__ void cp_commit() {
    asm volatile("cp.async.commit_group;" ::: "memory");
}
template <int N>
__device__ __forceinline__ void cp_wait() {
    asm volatile("cp.async.wait_group %0;" :: "n"(N) : "memory");
}

// B-frag word index within a (32k x 128n) tile for element (k_in 0..31, n_in 0..127)
__device__ __forceinline__ int bfrag_widx(int k_in, int n_in) {
    int ks = k_in >> 3, rem = k_in & 7, qc = rem & 3, e = rem >> 2;
    int wn = n_in >> 5, qr = n_in & 7, nf = (n_in >> 3) & 3;
    return (((ks * 4 + wn) * 32) + qr * 4 + qc) * 8 + nf * 2 + e;
}
#define FSWZ(w) ((w) ^ ((((uint32_t)(w)) >> 3) & 0x1Cu))

// ---------------- weight permute: fp32 [M][NC] -> tf32 A-frag-ready ----------------
__global__ __launch_bounds__(256) void wperm_kernel(const float* __restrict__ in,
                                                    float* __restrict__ out, int M) {
    int i = blockIdx.x * 256 + threadIdx.x;
    if (i >= M * NC) return;
    int m = i >> 9, k = i & 511;
    float v = tf32f(in[i]);
    int mt = m >> 7, mb = (m >> 4) & 7, r = m & 15, qr = r & 7;
    int kt = k >> 5, ks = (k >> 3) & 3, kc = k & 7, qc = kc & 3;
    int e = (r >> 3) | ((kc >> 2) << 1);
    size_t dst = ((size_t)(mt * 16 + kt) << 12) + ((ks * 8 + mb) << 7) + ((qr * 4 + qc) << 2) + e;
    out[dst] = v;
}

// ---------------- GroupNorm: stats + apply + tf32, writes B-frag-ready tiles ----------------
__global__ __launch_bounds__(256) void gn_kernel(const float* __restrict__ x,
                                                 const float* __restrict__ nw,
                                                 const float* __restrict__ nb) {
    int bg = blockIdx.x;
    int b = bg >> 5, g = bg & 31;
    const float4* p4 = (const float4*)(x + (size_t)bg * NGC * NT);
    float s = 0.f, ss = 0.f;
    for (int i = threadIdx.x; i < NGC * NT / 4; i += 256) {
        float4 v = p4[i];
        s  += v.x + v.y + v.z + v.w;
        ss += v.x * v.x + v.y * v.y + v.z * v.z + v.w * v.w;
    }
    __shared__ float sh[512];
    sh[threadIdx.x] = s;
    sh[256 + threadIdx.x] = ss;
    __syncthreads();
    for (int off = 128; off > 0; off >>= 1) {
        if (threadIdx.x < off) {
            sh[threadIdx.x]       += sh[threadIdx.x + off];
            sh[256 + threadIdx.x] += sh[256 + threadIdx.x + off];
        }
        __syncthreads();
    }
    float inv = 1.f / (float)(NGC * NT);
    float mu  = sh[0] * inv;
    float var = sh[256] * inv - mu * mu;
    float rs = rsqrtf(var + 1e-5f);
    float* outb = g_xn + (size_t)b * NC * NT;
    for (int i = threadIdx.x; i < NGC * NT / 4; i += 256) {
        int c = g * NGC + (i >> 8);       // global channel (k)
        int t4 = (i & 255) << 2;          // token (n)
        float sw = nw[c] * rs, sb = nb[c] - mu * sw;
        float4 v = p4[i];
        int kt = c >> 5, nt = t4 >> 7;
        float* tile = outb + (size_t)(kt * 8 + nt) * 4096;
        int w0 = bfrag_widx(c & 31, t4 & 127);   // t4%8 in {0,4}: +j => widx + j*32
        tile[w0]      = tf32f(v.x * sw + sb);
        tile[w0 + 32] = tf32f(v.y * sw + sb);
        tile[w0 + 64] = tf32f(v.z * sw + sb);
        tile[w0 + 96] = tf32f(v.w * sw + sb);
    }
}

// ---------------- TF32 mma.sync GEMM: frag-ready A and B, 3-stage cp.async ----------------
// Stage: A 4096 w + B 4096 w = 8192 w. B tile loads: 2x LDS.128 per ks per warp.
template <int MTOT, bool OUT_TF32, bool FUSE_RES>
__global__ __launch_bounds__(256, 2) void mma_gemm_kernel(
    const float* __restrict__ W, const float* __restrict__ Bsrc,
    const float* __restrict__ bias,
    const float* __restrict__ resid, float* __restrict__ Cout)
{
    extern __shared__ uint32_t smu[];
    const uint32_t sbase = (uint32_t)__cvta_generic_to_shared(smu);
    const int b = blockIdx.z, m0 = blockIdx.y << 7, n0 = blockIdx.x << 7;
    const float* Bb = Bsrc + (size_t)b * NC * NT;
    const float* Wt0 = W + ((size_t)(m0 >> 7) << 4 << 12);
    const int tid = threadIdx.x, lane = tid & 31, warp = tid >> 5;
    const int wm = warp >> 2, wn = warp & 3;
    const int qr = lane >> 2, qc = lane & 3;

    auto ISSUE = [&](int stage, int it) {
        uint32_t abase = sbase + (uint32_t)stage * 8192u * 4u;
        uint32_t bbase = abase + 4096u * 4u;
        const float* Wt = Wt0 + ((size_t)it << 12);
        const float* Bt = Bb + ((size_t)(it * 8 + blockIdx.x)) * 4096;
        #pragma unroll
        for (int r = 0; r < 4; r++) {
            int idx = tid + (r << 8);
            cp16(abase + (uint32_t)idx * 16u, Wt + idx * 4);
            cp16(bbase + (uint32_t)idx * 16u, Bt + idx * 4);
        }
    };

    float acc[4][4][4] = {};

    ISSUE(0, 0); cp_commit();
    ISSUE(1, 1); cp_commit();

    #pragma unroll 1
    for (int it = 0; it < 16; it++) {
        cp_wait<1>();
        __syncthreads();
        if (it + 2 < 16) ISSUE((it + 2) % 3, it + 2);
        cp_commit();

        const uint32_t* A  = smu + (it % 3) * 8192;
        const uint32_t* Bs = A + 4096;
        #pragma unroll
        for (int ks = 0; ks < 4; ks++) {
            uint4 af[4];
            #pragma unroll
            for (int mf = 0; mf < 4; mf++)
                af[mf] = *(const uint4*)&A[((ks * 8 + wm * 4 + mf) << 7) + (lane << 2)];
            const uint32_t* bp = Bs + ((ks * 4 + wn) << 8) + (lane << 3);
            uint4 b01 = *(const uint4*)bp;
            uint4 b23 = *(const uint4*)(bp + 4);
            uint32_t bf[4][2] = {{b01.x, b01.y}, {b01.z, b01.w},
                                 {b23.x, b23.y}, {b23.z, b23.w}};
            #pragma unroll
            for (int mf = 0; mf < 4; mf++)
                #pragma unroll
                for (int nf = 0; nf < 4; nf++)
                    mma_tf32(acc[mf][nf], (const uint32_t*)&af[mf], bf[nf]);
        }
    }

    #pragma unroll
    for (int mf = 0; mf < 4; mf++) {
        int m_r = m0 + wm * 64 + mf * 16 + qr;
        float bv0 = bias[m_r], bv1 = bias[m_r + 8];
        #pragma unroll
        for (int nf = 0; nf < 4; nf++) {
            int n = n0 + wn * 32 + nf * 8 + 2 * qc;
            float2 v0 = { acc[mf][nf][0] + bv0, acc[mf][nf][1] + bv0 };
            float2 v1 = { acc[mf][nf][2] + bv1, acc[mf][nf][3] + bv1 };
            if (FUSE_RES) {
                float2 r0 = *(const float2*)(resid + ((size_t)b * NC + m_r) * NT + n);
                float2 r1 = *(const float2*)(resid + ((size_t)b * NC + m_r + 8) * NT + n);
                v0.x += r0.x; v0.y += r0.y;
                v1.x += r1.x; v1.y += r1.y;
            }
            if (OUT_TF32) {
                v0.x = tf32f(v0.x); v0.y = tf32f(v0.y);
                v1.x = tf32f(v1.x); v1.y = tf32f(v1.y);
            }
            *(float2*)(Cout + ((size_t)b * MTOT + m_r) * NT + n) = v0;
            *(float2*)(Cout + ((size_t)b * MTOT + m_r + 8) * NT + n) = v1;
        }
    }
}

// ---------------- flash attention: 128-q tile, 32 q/warp, 32-s chunks ----------------
// Epilogue writes g_attn in B-frag-ready tiles (for proj GEMM) via swizzled smem stage.
__global__ __launch_bounds__(128, 2) void attn_kernel() {
    extern __shared__ uint32_t smw[];
    const uint32_t sbase = (uint32_t)__cvta_generic_to_shared(smw);
    uint32_t* const P0 = smw;   // Q stage [64][132] -> P [128][36] -> O frag-stage 8192
    uint32_t* const Ks[2] = { smw + 8448, smw + 8448 + 2304 };
    uint32_t* const Vs[2] = { smw + 8448 + 2 * 2304, smw + 8448 + 3 * 2304 };

    const int qt0 = blockIdx.x << 7;
    const int bh = blockIdx.y;
    const int b = bh >> 3, h = bh & 7;
    const float* qp = g_qkv + ((size_t)b * 3 * NC + (size_t)h * 3 * NCH) * NT;
    const float* kp = qp + (size_t)NCH * NT;
    const float* vp = kp + (size_t)NCH * NT;

    const int tid = threadIdx.x, lane = tid & 31, w = tid >> 5;
    const int qr = lane >> 2, qc = lane & 3;
    const int q0 = w << 5;

    auto ISSUE_KV = [&](int buf, int s0) {
        uint32_t kb = sbase + (8448u + (uint32_t)buf * 2304u) * 4u;
        uint32_t vb = sbase + (8448u + (2u + (uint32_t)buf) * 2304u) * 4u;
        #pragma unroll
        for (int r = 0; r < 4; r++) {
            int idx = tid + (r << 7);
            int c = idx >> 3, s4 = (idx & 7) << 2;
            uint32_t off = ((uint32_t)c * 36u + s4) * 4u;
            cp16(kb + off, kp + (size_t)c * NT + s0 + s4);
            cp16(vb + off, vp + (size_t)c * NT + s0 + s4);
        }
    };

    #pragma unroll
    for (int r = 0; r < 16; r++) {
        int idx = tid + (r << 7);
        int c = idx >> 5, t4 = (idx & 31) << 2;
        cp16(sbase + ((uint32_t)c * 132u + t4) * 4u, qp + (size_t)c * NT + qt0 + t4);
    }
    cp_commit();
    ISSUE_KV(0, 0); cp_commit();
    ISSUE_KV(1, 32); cp_commit();

    cp_wait<2>();
    __syncthreads();
    uint32_t qf[2][8][4];
    #pragma unroll
    for (int ks = 0; ks < 8; ks++) {
        int c = ks * 8 + qc;
        #pragma unroll
        for (int mf = 0; mf < 2; mf++) {
            int qq = q0 + mf * 16 + qr;
            qf[mf][ks][0] = __float_as_uint(__uint_as_float(P0[c * 132 + qq]) * 0.125f);
            qf[mf][ks][1] = __float_as_uint(__uint_as_float(P0[c * 132 + qq + 8]) * 0.125f);
            qf[mf][ks][2] = __float_as_uint(__uint_as_float(P0[(c + 4) * 132 + qq]) * 0.125f);
            qf[mf][ks][3] = __float_as_uint(__uint_as_float(P0[(c + 4) * 132 + qq + 8]) * 0.125f);
        }
    }

    float m_i[2][2] = {{-1e30f, -1e30f}, {-1e30f, -1e30f}};
    float l_i[2][2] = {{0.f, 0.f}, {0.f, 0.f}};
    float o[2][8][4] = {};

    #pragma unroll 1
    for (int i = 0; i < 32; i++) {
        const int buf = i & 1;
        cp_wait<1>();
        __syncthreads();

        const uint32_t* K = Ks[buf];
        const uint32_t* V = Vs[buf];

        float sf[2][4][4] = {};
        #pragma unroll
        for (int ks = 0; ks < 8; ks++) {
            int c = ks * 8 + qc;
            #pragma unroll
            for (int nf = 0; nf < 4; nf++) {
                uint32_t bb[2];
                int s = nf * 8 + qr;
                bb[0] = K[c * 36 + s];
                bb[1] = K[(c + 4) * 36 + s];
                mma_tf32(sf[0][nf], qf[0][ks], bb);
                mma_tf32(sf[1][nf], qf[1][ks], bb);
            }
        }

        #pragma unroll
        for (int mf = 0; mf < 2; mf++) {
            float mx0 = -1e30f, mx1 = -1e30f;
            #pragma unroll
            for (int nf = 0; nf < 4; nf++) {
                mx0 = fmaxf(mx0, fmaxf(sf[mf][nf][0], sf[mf][nf][1]));
                mx1 = fmaxf(mx1, fmaxf(sf[mf][nf][2], sf[mf][nf][3]));
            }
            #pragma unroll
            for (int off = 1; off <= 2; off <<= 1) {
                mx0 = fmaxf(mx0, __shfl_xor_sync(0xffffffffu, mx0, off));
                mx1 = fmaxf(mx1, __shfl_xor_sync(0xffffffffu, mx1, off));
            }
            float nm0 = fmaxf(m_i[mf][0], mx0), nm1 = fmaxf(m_i[mf][1], mx1);
            float corr0 = __expf(m_i[mf][0] - nm0), corr1 = __expf(m_i[mf][1] - nm1);
            m_i[mf][0] = nm0; m_i[mf][1] = nm1;
            float sum0 = 0.f, sum1 = 0.f;
            #pragma unroll
            for (int nf = 0; nf < 4; nf++) {
                sf[mf][nf][0] = __expf(sf[mf][nf][0] - nm0);
                sf[mf][nf][1] = __expf(sf[mf][nf][1] - nm0);
                sf[mf][nf][2] = __expf(sf[mf][nf][2] - nm1);
                sf[mf][nf][3] = __expf(sf[mf][nf][3] - nm1);
                sum0 += sf[mf][nf][0] + sf[mf][nf][1];
                sum1 += sf[mf][nf][2] + sf[mf][nf][3];
            }
            #pragma unroll
            for (int off = 1; off <= 2; off <<= 1) {
                sum0 += __shfl_xor_sync(0xffffffffu, sum0, off);
                sum1 += __shfl_xor_sync(0xffffffffu, sum1, off);
            }
            l_i[mf][0] = l_i[mf][0] * corr0 + sum0;
            l_i[mf][1] = l_i[mf][1] * corr1 + sum1;
            #pragma unroll
            for (int nf = 0; nf < 8; nf++) {
                o[mf][nf][0] *= corr0; o[mf][nf][1] *= corr0;
                o[mf][nf][2] *= corr1; o[mf][nf][3] *= corr1;
            }
        }

        #pragma unroll
        for (int mf = 0; mf < 2; mf++) {
            int qq = q0 + mf * 16 + qr;
            #pragma unroll
            for (int nf = 0; nf < 4; nf++) {
                int sc = nf * 8 + 2 * qc;
                *(uint2*)&P0[qq * 36 + sc] =
                    make_uint2(f2tf32(sf[mf][nf][0]), f2tf32(sf[mf][nf][1]));
                *(uint2*)&P0[(qq + 8) * 36 + sc] =
                    make_uint2(f2tf32(sf[mf][nf][2]), f2tf32(sf[mf][nf][3]));
            }
        }
        __syncwarp();

        #pragma unroll
        for (int ks = 0; ks < 4; ks++) {
            int s = ks * 8 + qc;
            uint32_t a0[4], a1[4];
            {
                int qq = q0 + qr;
                a0[0] = P0[qq * 36 + s];       a0[1] = P0[(qq + 8) * 36 + s];
                a0[2] = P0[qq * 36 + s + 4];   a0[3] = P0[(qq + 8) * 36 + s + 4];
                qq = q0 + 16 + qr;
                a1[0] = P0[qq * 36 + s];       a1[1] = P0[(qq + 8) * 36 + s];
                a1[2] = P0[qq * 36 + s + 4];   a1[3] = P0[(qq + 8) * 36 + s + 4];
            }
            #pragma unroll
            for (int nf = 0; nf < 8; nf++) {
                uint32_t bb[2];
                int c = nf * 8 + qr;
                bb[0] = V[c * 36 + s];
                bb[1] = V[c * 36 + s + 4];
                mma_tf32(o[0][nf], a0, bb);
                mma_tf32(o[1][nf], a1, bb);
            }
        }
        __syncthreads();
        if (i + 2 < 32) ISSUE_KV(buf, (i + 2) << 5);
        cp_commit();
    }

    // ---- epilogue: normalize, stage into B-frag layout (XOR swizzle), coalesced copy ----
    float inv00 = 1.f / l_i[0][0], inv01 = 1.f / l_i[0][1];
    float inv10 = 1.f / l_i[1][0], inv11 = 1.f / l_i[1][1];
    __syncthreads();
    #pragma unroll
    for (int mf = 0; mf < 2; mf++) {
        float i0 = mf ? inv10 : inv00, i1 = mf ? inv11 : inv01;
        int qq = q0 + mf * 16 + qr;
        #pragma unroll
        for (int nf = 0; nf < 8; nf++) {
            int c = nf * 8 + 2 * qc;
            // element (c,t): widx = (c>>5)*4096 + bfrag_widx(c&31, t)
            int w00 = ((c >> 5) << 12) + bfrag_widx(c & 31, qq);
            int w10 = (((c + 1) >> 5) << 12) + bfrag_widx((c + 1) & 31, qq);
            int w01 = ((c >> 5) << 12) + bfrag_widx(c & 31, qq + 8);
            int w11 = (((c + 1) >> 5) << 12) + bfrag_widx((c + 1) & 31, qq + 8);
            P0[FSWZ(w00)] = f2tf32(o[mf][nf][0] * i0);
            P0[FSWZ(w10)] = f2tf32(o[mf][nf][1] * i0);
            P0[FSWZ(w01)] = f2tf32(o[mf][nf][2] * i1);
            P0[FSWZ(w11)] = f2tf32(o[mf][nf][3] * i1);
        }
    }
    __syncthreads();
    // copy out: kt = h*2 + kt_loc, nt = blockIdx.x
    float* outp = g_attn + (size_t)b * NC * NT + (size_t)(h * 2 * 8 + blockIdx.x) * 4096;
    #pragma unroll
    for (int r = 0; r < 16; r++) {
        int widx = (tid + (r << 7)) << 2;               // 0..8188
        int kt_loc = widx >> 12;
        float4 v = *(const float4*)&((const float*)P0)[FSWZ(widx)];
        *(float4*)(outp + (size_t)kt_loc * 8 * 4096 + (widx & 4095) - (size_t)kt_loc * 4096 + (size_t)kt_loc * 4096) = v;
    }
}

// ---------------- launch ----------------
extern "C" void kernel_launch(void* const* d_in, const int* in_sizes, int n_in,
                              void* d_out, int out_size) {
    const float* x      = (const float*)d_in[0];
    const float* norm_w = (const float*)d_in[1];
    const float* norm_b = (const float*)d_in[2];
    const float* qkv_w  = (const float*)d_in[3];
    const float* qkv_b  = (const float*)d_in[4];
    const float* proj_w = (const float*)d_in[5];
    const float* proj_b = (const float*)d_in[6];
    float* out = (float*)d_out;

    float *xn_p, *wq_p, *wp_p, *qkv_p, *attn_p;
    cudaGetSymbolAddress((void**)&xn_p, g_xn);
    cudaGetSymbolAddress((void**)&wq_p, g_wq);
    cudaGetSymbolAddress((void**)&wp_p, g_wp);
    cudaGetSymbolAddress((void**)&qkv_p, g_qkv);
    cudaGetSymbolAddress((void**)&attn_p, g_attn);

    const int gemm_smem = 3 * 8192 * 4;   // 98304
    cudaFuncSetAttribute(mma_gemm_kernel<3 * NC, true, false>,
                         cudaFuncAttributeMaxDynamicSharedMemorySize, gemm_smem);
    cudaFuncSetAttribute(mma_gemm_kernel<NC, false, true>,
                         cudaFuncAttributeMaxDynamicSharedMemorySize, gemm_smem);
    const int attn_smem = (8448 + 4 * 2304) * 4;  // 70656
    cudaFuncSetAttribute(attn_kernel, cudaFuncAttributeMaxDynamicSharedMemorySize, attn_smem);

    wperm_kernel<<<(3 * NC * NC + 255) / 256, 256>>>(qkv_w, wq_p, 3 * NC);
    wperm_kernel<<<(NC * NC + 255) / 256, 256>>>(proj_w, wp_p, NC);
    gn_kernel<<<NB * NGROUPS, 256>>>(x, norm_w, norm_b);

    dim3 gq(NT / 128, (3 * NC) / 128, NB);
    mma_gemm_kernel<3 * NC, true, false><<<gq, 256, gemm_smem>>>(
        wq_p, xn_p, qkv_b, nullptr, qkv_p);

    dim3 ga(NT / 128, NB * NHEADS);
    attn_kernel<<<ga, 128, attn_smem>>>();

    dim3 gp(NT / 128, NC / 128, NB);
    mma_gemm_kernel<NC, false, true><<<gp, 256, gemm_smem>>>(
        wp_p, attn_p, proj_b, x, out);
}

// round 8
// speedup vs baseline: 1.0346x; 1.0346x over previous
#include <cuda_runtime.h>
#include <cstdint>

#define NB 8
#define NC 512
#define NT 1024
#define NHEADS 8
#define NCH 64
#define NGROUPS 32
#define NGC 16

// ---------------- scratch (alloc-free: __device__ globals) ----------------
__device__ float g_xn[(size_t)NB * NC * NT];        // 16 MB, tf32 bits, natural [b][c][t]
__device__ float g_wq[(size_t)3 * NC * NC];         // 3 MB,  tf32 bits, A-frag-ready
__device__ float g_wp[(size_t)NC * NC];             // 1 MB,  tf32 bits, A-frag-ready
__device__ float g_qkv[(size_t)NB * 3 * NC * NT];   // 48 MB, tf32 bits, natural
__device__ float g_attn[(size_t)NB * NC * NT];      // 16 MB, tf32 bits, natural

// ---------------- helpers ----------------
__device__ __forceinline__ uint32_t f2tf32(float f) {
    uint32_t r;
    asm("cvt.rna.tf32.f32 %0, %1;" : "=r"(r) : "f"(f));
    return r;
}
__device__ __forceinline__ float tf32f(float f) { return __uint_as_float(f2tf32(f)); }
__device__ __forceinline__ void mma_tf32(float* d, const uint32_t* a, const uint32_t* b) {
    asm volatile(
        "mma.sync.aligned.m16n8k8.row.col.f32.tf32.tf32.f32 "
        "{%0,%1,%2,%3}, {%4,%5,%6,%7}, {%8,%9}, {%0,%1,%2,%3};"
        : "+f"(d[0]), "+f"(d[1]), "+f"(d[2]), "+f"(d[3])
        : "r"(a[0]), "r"(a[1]), "r"(a[2]), "r"(a[3]), "r"(b[0]), "r"(b[1]));
}
__device__ __forceinline__ void cp16(uint32_t dst, const void* src) {
    asm volatile("cp.async.cg.shared.global [%0], [%1], 16;" :: "r"(dst), "l"(src));
}
__device__ __forceinline__ void cp_commit() {
    asm volatile("cp.async.commit_group;" ::: "memory");
}
template <int N>
__device__ __forceinline__ void cp_wait() {
    asm volatile("cp.async.wait_group %0;" :: "n"(N) : "memory");
}

// ---------------- weight permute (inverted: coalesced writes, L1-cached gathers) ----------------
// One block per output tile (mt,kt) = 4096 words. dst word w in tile:
//   w = (ks*8+mb)*128 + lane*4 + e ; element e of lane (qr*4+qc) of frag (mb,ks)
__global__ __launch_bounds__(256) void wperm_kernel(const float* __restrict__ in,
                                                    float* __restrict__ out) {
    int tile = blockIdx.x;           // mt*16 + kt
    int mt = tile >> 4, kt = tile & 15;
    float* dst = out + ((size_t)tile << 12);
    #pragma unroll
    for (int r = 0; r < 4; r++) {
        int w = (threadIdx.x + (r << 8)) << 2;
        int ks = w >> 10, mb = (w >> 7) & 7, lane = (w >> 2) & 31;
        int qr = lane >> 2, qc = lane & 3;
        int m0 = mt * 128 + mb * 16 + qr;
        int k0 = kt * 32 + ks * 8 + qc;
        float4 o;
        o.x = tf32f(in[(size_t)m0 * NC + k0]);
        o.y = tf32f(in[(size_t)(m0 + 8) * NC + k0]);
        o.z = tf32f(in[(size_t)m0 * NC + k0 + 4]);
        o.w = tf32f(in[(size_t)(m0 + 8) * NC + k0 + 4]);
        *(float4*)(dst + w) = o;
    }
}

// ---------------- GroupNorm: stats + apply + tf32 convert (natural layout) ----------------
__global__ __launch_bounds__(256) void gn_kernel(const float* __restrict__ x,
                                                 const float* __restrict__ nw,
                                                 const float* __restrict__ nb) {
    int bg = blockIdx.x;
    int g = bg & (NGROUPS - 1);
    const float4* p4 = (const float4*)(x + (size_t)bg * NGC * NT);
    float4* o4 = (float4*)(g_xn + (size_t)bg * NGC * NT);
    float s = 0.f, ss = 0.f;
    for (int i = threadIdx.x; i < NGC * NT / 4; i += 256) {
        float4 v = p4[i];
        s  += v.x + v.y + v.z + v.w;
        ss += v.x * v.x + v.y * v.y + v.z * v.z + v.w * v.w;
    }
    __shared__ float sh[512];
    sh[threadIdx.x] = s;
    sh[256 + threadIdx.x] = ss;
    __syncthreads();
    for (int off = 128; off > 0; off >>= 1) {
        if (threadIdx.x < off) {
            sh[threadIdx.x]       += sh[threadIdx.x + off];
            sh[256 + threadIdx.x] += sh[256 + threadIdx.x + off];
        }
        __syncthreads();
    }
    float inv = 1.f / (float)(NGC * NT);
    float mu  = sh[0] * inv;
    float var = sh[256] * inv - mu * mu;
    float rs = rsqrtf(var + 1e-5f);
    for (int i = threadIdx.x; i < NGC * NT / 4; i += 256) {
        int c = g * NGC + (i >> 8);
        float sw = nw[c] * rs, sb = nb[c] - mu * sw;
        float4 v = p4[i];
        v.x = tf32f(v.x * sw + sb); v.y = tf32f(v.y * sw + sb);
        v.z = tf32f(v.z * sw + sb); v.w = tf32f(v.w * sw + sb);
        o4[i] = v;
    }
}

// ---------------- TF32 mma.sync GEMM, 3-stage cp.async, frag-ready A, [32][136] B ----------------
template <int MTOT, bool OUT_TF32, bool FUSE_RES>
__global__ __launch_bounds__(256, 2) void mma_gemm_kernel(
    const float* __restrict__ W, const float* __restrict__ Bsrc,
    const float* __restrict__ bias,
    const float* __restrict__ resid, float* __restrict__ Cout)
{
    extern __shared__ uint32_t smu[];
    const uint32_t sbase = (uint32_t)__cvta_generic_to_shared(smu);
    const int b = blockIdx.z, m0 = blockIdx.y << 7, n0 = blockIdx.x << 7;
    const float* Bb = Bsrc + (size_t)b * NC * NT;
    const float* Wt0 = W + ((size_t)(m0 >> 7) << 4 << 12);
    const int tid = threadIdx.x, lane = tid & 31, warp = tid >> 5;
    const int wm = warp >> 2, wn = warp & 3;
    const int qr = lane >> 2, qc = lane & 3;

    auto ISSUE = [&](int stage, int it) {
        uint32_t abase = sbase + (uint32_t)stage * 8448u * 4u;
        uint32_t bbase = abase + 4096u * 4u;
        const float* Wt = Wt0 + ((size_t)it << 12);
        const int k0 = it << 5;
        #pragma unroll
        for (int r = 0; r < 4; r++) {
            int idx = tid + (r << 8);
            cp16(abase + (uint32_t)idx * 16u, Wt + idx * 4);
            int k = idx >> 5, n4 = (idx & 31) << 2;
            cp16(bbase + ((uint32_t)k * 136u + n4) * 4u,
                 Bb + (size_t)(k0 + k) * NT + n0 + n4);
        }
    };

    float acc[4][4][4] = {};

    ISSUE(0, 0); cp_commit();
    ISSUE(1, 1); cp_commit();

    #pragma unroll 1
    for (int it = 0; it < 16; it++) {
        cp_wait<1>();
        __syncthreads();
        if (it + 2 < 16) ISSUE((it + 2) % 3, it + 2);
        cp_commit();

        const uint32_t* A  = smu + (it % 3) * 8448;
        const uint32_t* Bs = A + 4096;
        #pragma unroll
        for (int ks = 0; ks < 4; ks++) {
            uint4 af[4];
            uint32_t bf[4][2];
            #pragma unroll
            for (int mf = 0; mf < 4; mf++)
                af[mf] = *(const uint4*)&A[((ks * 8 + wm * 4 + mf) << 7) + (lane << 2)];
            #pragma unroll
            for (int nf = 0; nf < 4; nf++) {
                int n = wn * 32 + nf * 8 + qr, k = ks * 8 + qc;
                bf[nf][0] = Bs[k * 136 + n];
                bf[nf][1] = Bs[(k + 4) * 136 + n];
            }
            #pragma unroll
            for (int mf = 0; mf < 4; mf++)
                #pragma unroll
                for (int nf = 0; nf < 4; nf++)
                    mma_tf32(acc[mf][nf], (const uint32_t*)&af[mf], bf[nf]);
        }
    }

    #pragma unroll
    for (int mf = 0; mf < 4; mf++) {
        int m_r = m0 + wm * 64 + mf * 16 + qr;
        float bv0 = bias[m_r], bv1 = bias[m_r + 8];
        #pragma unroll
        for (int nf = 0; nf < 4; nf++) {
            int n = n0 + wn * 32 + nf * 8 + 2 * qc;
            float2 v0 = { acc[mf][nf][0] + bv0, acc[mf][nf][1] + bv0 };
            float2 v1 = { acc[mf][nf][2] + bv1, acc[mf][nf][3] + bv1 };
            if (FUSE_RES) {
                float2 r0 = *(const float2*)(resid + ((size_t)b * NC + m_r) * NT + n);
                float2 r1 = *(const float2*)(resid + ((size_t)b * NC + m_r + 8) * NT + n);
                v0.x += r0.x; v0.y += r0.y;
                v1.x += r1.x; v1.y += r1.y;
            }
            if (OUT_TF32) {
                v0.x = tf32f(v0.x); v0.y = tf32f(v0.y);
                v1.x = tf32f(v1.x); v1.y = tf32f(v1.y);
            }
            *(float2*)(Cout + ((size_t)b * MTOT + m_r) * NT + n) = v0;
            *(float2*)(Cout + ((size_t)b * MTOT + m_r + 8) * NT + n) = v1;
        }
    }
}

// ---------------- flash attention: 128-q tile, 32 q/warp, 32-s chunks, TRIPLE-buffered KV ----------------
// smem (words): [0,8448): Q stage [64][132] -> P [128][36] -> O stage [64][132]
//               K bufs 3x2304 at 8448; V bufs 3x2304 after.
__global__ __launch_bounds__(128, 2) void attn_kernel() {
    extern __shared__ uint32_t smw[];
    const uint32_t sbase = (uint32_t)__cvta_generic_to_shared(smw);
    uint32_t* const P0 = smw;
    uint32_t* const Ks[3] = { smw + 8448, smw + 8448 + 2304, smw + 8448 + 2 * 2304 };
    uint32_t* const Vs[3] = { smw + 8448 + 3 * 2304, smw + 8448 + 4 * 2304, smw + 8448 + 5 * 2304 };

    const int qt0 = blockIdx.x << 7;
    const int bh = blockIdx.y;
    const int b = bh >> 3, h = bh & 7;
    const float* qp = g_qkv + ((size_t)b * 3 * NC + (size_t)h * 3 * NCH) * NT;
    const float* kp = qp + (size_t)NCH * NT;
    const float* vp = kp + (size_t)NCH * NT;

    const int tid = threadIdx.x, lane = tid & 31, w = tid >> 5;
    const int qr = lane >> 2, qc = lane & 3;
    const int q0 = w << 5;

    auto ISSUE_KV = [&](int slot, int s0) {
        uint32_t kb = sbase + (8448u + (uint32_t)slot * 2304u) * 4u;
        uint32_t vb = sbase + (8448u + (3u + (uint32_t)slot) * 2304u) * 4u;
        #pragma unroll
        for (int r = 0; r < 4; r++) {
            int idx = tid + (r << 7);
            int c = idx >> 3, s4 = (idx & 7) << 2;
            uint32_t off = ((uint32_t)c * 36u + s4) * 4u;
            cp16(kb + off, kp + (size_t)c * NT + s0 + s4);
            cp16(vb + off, vp + (size_t)c * NT + s0 + s4);
        }
    };

    // prologue: Q (group0), KV slot0 (g1), KV slot1 (g2)
    #pragma unroll
    for (int r = 0; r < 16; r++) {
        int idx = tid + (r << 7);
        int c = idx >> 5, t4 = (idx & 31) << 2;
        cp16(sbase + ((uint32_t)c * 132u + t4) * 4u, qp + (size_t)c * NT + qt0 + t4);
    }
    cp_commit();
    ISSUE_KV(0, 0); cp_commit();
    ISSUE_KV(1, 32); cp_commit();

    // hoist Q fragments (scaled by 1/8: exponent-only, exact)
    cp_wait<2>();
    __syncthreads();
    uint32_t qf[2][8][4];
    #pragma unroll
    for (int ks = 0; ks < 8; ks++) {
        int c = ks * 8 + qc;
        #pragma unroll
        for (int mf = 0; mf < 2; mf++) {
            int qq = q0 + mf * 16 + qr;
            qf[mf][ks][0] = __float_as_uint(__uint_as_float(P0[c * 132 + qq]) * 0.125f);
            qf[mf][ks][1] = __float_as_uint(__uint_as_float(P0[c * 132 + qq + 8]) * 0.125f);
            qf[mf][ks][2] = __float_as_uint(__uint_as_float(P0[(c + 4) * 132 + qq]) * 0.125f);
            qf[mf][ks][3] = __float_as_uint(__uint_as_float(P0[(c + 4) * 132 + qq + 8]) * 0.125f);
        }
    }

    float m_i[2][2] = {{-1e30f, -1e30f}, {-1e30f, -1e30f}};
    float l_i[2][2] = {{0.f, 0.f}, {0.f, 0.f}};
    float o[2][8][4] = {};

    #pragma unroll 1
    for (int i = 0; i < 32; i++) {
        const int slot = i % 3;
        cp_wait<1>();
        __syncthreads();   // fences prior-iter readers of refill target AND Q-hoist (i=0)

        const uint32_t* K = Ks[slot];
        const uint32_t* V = Vs[slot];

        float sf[2][4][4] = {};
        #pragma unroll
        for (int ks = 0; ks < 8; ks++) {
            int c = ks * 8 + qc;
            #pragma unroll
            for (int nf = 0; nf < 4; nf++) {
                uint32_t bb[2];
                int s = nf * 8 + qr;
                bb[0] = K[c * 36 + s];
                bb[1] = K[(c + 4) * 36 + s];
                mma_tf32(sf[0][nf], qf[0][ks], bb);
                mma_tf32(sf[1][nf], qf[1][ks], bb);
            }
        }

        #pragma unroll
        for (int mf = 0; mf < 2; mf++) {
            float mx0 = -1e30f, mx1 = -1e30f;
            #pragma unroll
            for (int nf = 0; nf < 4; nf++) {
                mx0 = fmaxf(mx0, fmaxf(sf[mf][nf][0], sf[mf][nf][1]));
                mx1 = fmaxf(mx1, fmaxf(sf[mf][nf][2], sf[mf][nf][3]));
            }
            #pragma unroll
            for (int off = 1; off <= 2; off <<= 1) {
                mx0 = fmaxf(mx0, __shfl_xor_sync(0xffffffffu, mx0, off));
                mx1 = fmaxf(mx1, __shfl_xor_sync(0xffffffffu, mx1, off));
            }
            float nm0 = fmaxf(m_i[mf][0], mx0), nm1 = fmaxf(m_i[mf][1], mx1);
            float corr0 = __expf(m_i[mf][0] - nm0), corr1 = __expf(m_i[mf][1] - nm1);
            m_i[mf][0] = nm0; m_i[mf][1] = nm1;
            float sum0 = 0.f, sum1 = 0.f;
            #pragma unroll
            for (int nf = 0; nf < 4; nf++) {
                sf[mf][nf][0] = __expf(sf[mf][nf][0] - nm0);
                sf[mf][nf][1] = __expf(sf[mf][nf][1] - nm0);
                sf[mf][nf][2] = __expf(sf[mf][nf][2] - nm1);
                sf[mf][nf][3] = __expf(sf[mf][nf][3] - nm1);
                sum0 += sf[mf][nf][0] + sf[mf][nf][1];
                sum1 += sf[mf][nf][2] + sf[mf][nf][3];
            }
            #pragma unroll
            for (int off = 1; off <= 2; off <<= 1) {
                sum0 += __shfl_xor_sync(0xffffffffu, sum0, off);
                sum1 += __shfl_xor_sync(0xffffffffu, sum1, off);
            }
            l_i[mf][0] = l_i[mf][0] * corr0 + sum0;
            l_i[mf][1] = l_i[mf][1] * corr1 + sum1;
            #pragma unroll
            for (int nf = 0; nf < 8; nf++) {
                o[mf][nf][0] *= corr0; o[mf][nf][1] *= corr0;
                o[mf][nf][2] *= corr1; o[mf][nf][3] *= corr1;
            }
        }

        // P -> warp-private smem rows [q0, q0+32), stride 36
        #pragma unroll
        for (int mf = 0; mf < 2; mf++) {
            int qq = q0 + mf * 16 + qr;
            #pragma unroll
            for (int nf = 0; nf < 4; nf++) {
                int sc = nf * 8 + 2 * qc;
                *(uint2*)&P0[qq * 36 + sc] =
                    make_uint2(f2tf32(sf[mf][nf][0]), f2tf32(sf[mf][nf][1]));
                *(uint2*)&P0[(qq + 8) * 36 + sc] =
                    make_uint2(f2tf32(sf[mf][nf][2]), f2tf32(sf[mf][nf][3]));
            }
        }
        __syncwarp();

        #pragma unroll
        for (int ks = 0; ks < 4; ks++) {
            int s = ks * 8 + qc;
            uint32_t a0[4], a1[4];
            {
                int qq = q0 + qr;
                a0[0] = P0[qq * 36 + s];       a0[1] = P0[(qq + 8) * 36 + s];
                a0[2] = P0[qq * 36 + s + 4];   a0[3] = P0[(qq + 8) * 36 + s + 4];
                qq = q0 + 16 + qr;
                a1[0] = P0[qq * 36 + s];       a1[1] = P0[(qq + 8) * 36 + s];
                a1[2] = P0[qq * 36 + s + 4];   a1[3] = P0[(qq + 8) * 36 + s + 4];
            }
            #pragma unroll
            for (int nf = 0; nf < 8; nf++) {
                uint32_t bb[2];
                int c = nf * 8 + qr;
                bb[0] = V[c * 36 + s];
                bb[1] = V[c * 36 + s + 4];
                mma_tf32(o[0][nf], a0, bb);
                mma_tf32(o[1][nf], a1, bb);
            }
        }

        if (i + 2 < 32) ISSUE_KV((i + 2) % 3, (i + 2) << 5);
        cp_commit();
    }

    // epilogue: normalize, tf32, stage [c][t] stride 132, coalesced store
    float inv00 = 1.f / l_i[0][0], inv01 = 1.f / l_i[0][1];
    float inv10 = 1.f / l_i[1][0], inv11 = 1.f / l_i[1][1];
    __syncthreads();
    float* Os = (float*)P0;
    #pragma unroll
    for (int mf = 0; mf < 2; mf++) {
        float i0 = mf ? inv10 : inv00, i1 = mf ? inv11 : inv01;
        int qq = q0 + mf * 16 + qr;
        #pragma unroll
        for (int nf = 0; nf < 8; nf++) {
            int c = nf * 8 + 2 * qc;
            Os[c * 132 + qq]           = tf32f(o[mf][nf][0] * i0);
            Os[(c + 1) * 132 + qq]     = tf32f(o[mf][nf][1] * i0);
            Os[c * 132 + qq + 8]       = tf32f(o[mf][nf][2] * i1);
            Os[(c + 1) * 132 + qq + 8] = tf32f(o[mf][nf][3] * i1);
        }
    }
    __syncthreads();
    float* outp = g_attn + ((size_t)b * NC + (size_t)h * NCH) * NT;
    #pragma unroll
    for (int r = 0; r < 16; r++) {
        int idx = tid + (r << 7);
        int c = idx >> 5, t4 = (idx & 31) << 2;
        *(float4*)(outp + (size_t)c * NT + qt0 + t4) = *(const float4*)&Os[c * 132 + t4];
    }
}

// ---------------- launch ----------------
extern "C" void kernel_launch(void* const* d_in, const int* in_sizes, int n_in,
                              void* d_out, int out_size) {
    const float* x      = (const float*)d_in[0];
    const float* norm_w = (const float*)d_in[1];
    const float* norm_b = (const float*)d_in[2];
    const float* qkv_w  = (const float*)d_in[3];
    const float* qkv_b  = (const float*)d_in[4];
    const float* proj_w = (const float*)d_in[5];
    const float* proj_b = (const float*)d_in[6];
    float* out = (float*)d_out;

    float *xn_p, *wq_p, *wp_p, *qkv_p, *attn_p;
    cudaGetSymbolAddress((void**)&xn_p, g_xn);
    cudaGetSymbolAddress((void**)&wq_p, g_wq);
    cudaGetSymbolAddress((void**)&wp_p, g_wp);
    cudaGetSymbolAddress((void**)&qkv_p, g_qkv);
    cudaGetSymbolAddress((void**)&attn_p, g_attn);

    const int gemm_smem = 3 * 8448 * 4;   // 101376
    cudaFuncSetAttribute(mma_gemm_kernel<3 * NC, true, false>,
                         cudaFuncAttributeMaxDynamicSharedMemorySize, gemm_smem);
    cudaFuncSetAttribute(mma_gemm_kernel<NC, false, true>,
                         cudaFuncAttributeMaxDynamicSharedMemorySize, gemm_smem);
    const int attn_smem = (8448 + 6 * 2304) * 4;  // 89088
    cudaFuncSetAttribute(attn_kernel, cudaFuncAttributeMaxDynamicSharedMemorySize, attn_smem);

    wperm_kernel<<<(3 * NC / 128) * 16, 256>>>(qkv_w, wq_p);
    wperm_kernel<<<(NC / 128) * 16, 256>>>(proj_w, wp_p);
    gn_kernel<<<NB * NGROUPS, 256>>>(x, norm_w, norm_b);

    dim3 gq(NT / 128, (3 * NC) / 128, NB);
    mma_gemm_kernel<3 * NC, true, false><<<gq, 256, gemm_smem>>>(
        wq_p, xn_p, qkv_b, nullptr, qkv_p);

    dim3 ga(NT / 128, NB * NHEADS);
    attn_kernel<<<ga, 128, attn_smem>>>();

    dim3 gp(NT / 128, NC / 128, NB);
    mma_gemm_kernel<NC, false, true><<<gp, 256, gemm_smem>>>(
        wp_p, attn_p, proj_b, x, out);
}